// round 1
// baseline (speedup 1.0000x reference)
#include <cuda_runtime.h>
#include <cuda_bf16.h>
#include <math.h>

// ---------------------------------------------------------------------------
// Problem constants
// ---------------------------------------------------------------------------
#define B 8
#define SEQ 1024
#define NROW 32
#define NCOL 32
#define WIN 9
#define D 512
#define DFF 1024
#define VOCAB 16384
#define NTOK (B * SEQ)   // 8192
#define EPS 1e-5f

// ---------------------------------------------------------------------------
// Scratch buffers (device globals: no allocation allowed)
// ---------------------------------------------------------------------------
__device__ float g_h0 [NTOK * D];    // embed + pos
__device__ float g_q  [NTOK * D];
__device__ float g_k  [NTOK * D];
__device__ float g_v  [NTOK * D];
__device__ float g_att[NTOK * D];    // attention output (pre O-proj)
__device__ float g_o  [NTOK * D];    // O-proj output
__device__ float g_h1 [NTOK * D];    // after LN1
__device__ float g_mid[NTOK * DFF];  // FFN hidden
__device__ float g_f  [NTOK * D];    // FFN output
__device__ float g_h2 [NTOK * D];    // after LN2

// ---------------------------------------------------------------------------
// Kernel 1: embedding gather + 2D positional encoding
// h0[b,s,:] = embed_tab[x[b,s],:] + [row_embed[s/32,:], col_embed[s%32,:]]
// one block (128 thr) per token row; float4 vectorized
// ---------------------------------------------------------------------------
__global__ void embed_kernel(const int* __restrict__ x,
                             const float* __restrict__ tab,
                             const float* __restrict__ rowe,
                             const float* __restrict__ cole,
                             float* __restrict__ h) {
    int qi = blockIdx.x;             // 0..8191
    int s  = qi & (SEQ - 1);
    int r  = s >> 5, c = s & 31;
    int tok = x[qi];
    int d = threadIdx.x * 4;

    float4 e = *(const float4*)&tab[(size_t)tok * D + d];
    float4 p;
    if (d < D / 2) p = *(const float4*)&rowe[r * (D / 2) + d];
    else           p = *(const float4*)&cole[c * (D / 2) + (d - D / 2)];
    e.x += p.x; e.y += p.y; e.z += p.z; e.w += p.w;
    *(float4*)&h[(size_t)qi * D + d] = e;
}

// ---------------------------------------------------------------------------
// Kernel 2: generic fp32 GEMM + bias (+ optional ReLU)
//   C[M,N] = A[M,K] @ B[K,N] + bias[N]
// 128x128 tile, BK=8, 256 threads, 8x8 per thread.
// All M,N multiples of 128; K multiple of 8 (holds for every call here).
// ---------------------------------------------------------------------------
__global__ void gemm_bias(const float* __restrict__ A,
                          const float* __restrict__ Bm,
                          const float* __restrict__ bias,
                          float* __restrict__ C,
                          int M, int N, int K, int relu) {
    __shared__ float As[8][128];
    __shared__ float Bs[8][128];

    int tid = threadIdx.x;
    int bm = blockIdx.y * 128;
    int bn = blockIdx.x * 128;

    int arow = tid >> 1;             // 0..127
    int acol = (tid & 1) * 4;        // 0 or 4
    int brow = tid >> 5;             // 0..7
    int bcol = (tid & 31) * 4;       // 0..124

    int ty = tid >> 4;               // 0..15
    int tx = tid & 15;               // 0..15

    float acc[8][8];
#pragma unroll
    for (int i = 0; i < 8; i++)
#pragma unroll
        for (int j = 0; j < 8; j++) acc[i][j] = 0.0f;

    for (int k0 = 0; k0 < K; k0 += 8) {
        float4 av = *(const float4*)&A[(size_t)(bm + arow) * K + k0 + acol];
        As[acol + 0][arow] = av.x;
        As[acol + 1][arow] = av.y;
        As[acol + 2][arow] = av.z;
        As[acol + 3][arow] = av.w;
        float4 bv = *(const float4*)&Bm[(size_t)(k0 + brow) * N + bn + bcol];
        *(float4*)&Bs[brow][bcol] = bv;
        __syncthreads();

#pragma unroll
        for (int kk = 0; kk < 8; kk++) {
            float a[8], bb[8];
#pragma unroll
            for (int i = 0; i < 8; i++) a[i] = As[kk][ty * 8 + i];
#pragma unroll
            for (int j = 0; j < 8; j++) bb[j] = Bs[kk][tx * 8 + j];
#pragma unroll
            for (int i = 0; i < 8; i++)
#pragma unroll
                for (int j = 0; j < 8; j++) acc[i][j] = fmaf(a[i], bb[j], acc[i][j]);
        }
        __syncthreads();
    }

#pragma unroll
    for (int i = 0; i < 8; i++) {
        int row = bm + ty * 8 + i;
#pragma unroll
        for (int j = 0; j < 8; j += 4) {
            int col = bn + tx * 8 + j;
            float4 o;
            o.x = acc[i][j + 0] + bias[col + 0];
            o.y = acc[i][j + 1] + bias[col + 1];
            o.z = acc[i][j + 2] + bias[col + 2];
            o.w = acc[i][j + 3] + bias[col + 3];
            if (relu) {
                o.x = fmaxf(o.x, 0.0f); o.y = fmaxf(o.y, 0.0f);
                o.z = fmaxf(o.z, 0.0f); o.w = fmaxf(o.w, 0.0f);
            }
            *(float4*)&C[(size_t)row * N + col] = o;
        }
    }
}

// ---------------------------------------------------------------------------
// Kernel 3: fused local-causal attention.
// One block (128 thr) per query token. Allowed keys: rows r-9..r, cols c-9..c+9,
// row r truncated at col c (causal). <= 181 keys.
// ---------------------------------------------------------------------------
__global__ void attn_kernel(const float* __restrict__ Q,
                            const float* __restrict__ K,
                            const float* __restrict__ V,
                            float* __restrict__ O) {
    int qi = blockIdx.x;
    int b = qi >> 10, s = qi & (SEQ - 1);
    int r = s >> 5, c = s & 31;
    int r0 = (r - WIN < 0) ? 0 : r - WIN;
    int c0 = (c - WIN < 0) ? 0 : c - WIN;
    int c1 = (c + WIN > 31) ? 31 : c + WIN;
    int wcols = c1 - c0 + 1;
    int nfull = r - r0;
    int nk = nfull * wcols + (c - c0 + 1);

    __shared__ float qv[D];
    __shared__ float sc[256];
    __shared__ int   kid[256];
    __shared__ float red[4];

    int tid = threadIdx.x;
    int lane = tid & 31, wid = tid >> 5;

    // load q row
    *(float4*)&qv[tid * 4] = *(const float4*)&Q[(size_t)qi * D + tid * 4];
    __syncthreads();

    const float scale = 0.044194173824159216f;  // 1/sqrt(512)
    const float* kbase = K + (size_t)b * SEQ * D;

    // scores: warp w handles keys w, w+4, ...
    for (int j = wid; j < nk; j += 4) {
        int row, col;
        if (j < nfull * wcols) { row = r0 + j / wcols; col = c0 + j % wcols; }
        else                   { row = r;             col = c0 + (j - nfull * wcols); }
        int kk = row * 32 + col;
        const float* krow = kbase + (size_t)kk * D;
        float sum = 0.0f;
#pragma unroll
        for (int t = 0; t < D / 32; t++)
            sum = fmaf(qv[lane + 32 * t], krow[lane + 32 * t], sum);
#pragma unroll
        for (int off = 16; off; off >>= 1)
            sum += __shfl_xor_sync(0xffffffffu, sum, off);
        if (lane == 0) { sc[j] = sum * scale; kid[j] = kk; }
    }
    __syncthreads();

    // block max
    float m = -1e30f;
    for (int j = tid; j < nk; j += 128) m = fmaxf(m, sc[j]);
#pragma unroll
    for (int off = 16; off; off >>= 1)
        m = fmaxf(m, __shfl_xor_sync(0xffffffffu, m, off));
    if (lane == 0) red[wid] = m;
    __syncthreads();
    m = fmaxf(fmaxf(red[0], red[1]), fmaxf(red[2], red[3]));

    // exp + sum
    float ssum = 0.0f;
    for (int j = tid; j < nk; j += 128) {
        float e = __expf(sc[j] - m);
        sc[j] = e;
        ssum += e;
    }
    __syncthreads();   // covers red reuse + sc writes
#pragma unroll
    for (int off = 16; off; off >>= 1)
        ssum += __shfl_xor_sync(0xffffffffu, ssum, off);
    if (lane == 0) red[wid] = ssum;
    __syncthreads();
    float inv = 1.0f / (red[0] + red[1] + red[2] + red[3]);

    // weighted sum of V rows: thread t owns dims [4t, 4t+4)
    const float* vbase = V + (size_t)b * SEQ * D;
    int d = tid * 4;
    float4 acc = make_float4(0.f, 0.f, 0.f, 0.f);
    for (int j = 0; j < nk; j++) {
        float w = sc[j] * inv;
        float4 v = *(const float4*)&vbase[(size_t)kid[j] * D + d];
        acc.x = fmaf(w, v.x, acc.x);
        acc.y = fmaf(w, v.y, acc.y);
        acc.z = fmaf(w, v.z, acc.z);
        acc.w = fmaf(w, v.w, acc.w);
    }
    *(float4*)&O[(size_t)qi * D + d] = acc;
}

// ---------------------------------------------------------------------------
// Kernel 4: out = LayerNorm(X + Y) * g + b   (row-wise over D=512)
// One block (128 thr) per row.
// ---------------------------------------------------------------------------
__global__ void add_ln_kernel(const float* __restrict__ X,
                              const float* __restrict__ Y,
                              const float* __restrict__ g,
                              const float* __restrict__ beta,
                              float* __restrict__ out) {
    int row = blockIdx.x;
    int tid = threadIdx.x;
    int lane = tid & 31, wid = tid >> 5;
    __shared__ float reds[4], redq[4];

    int d = tid * 4;
    float4 xv = *(const float4*)&X[(size_t)row * D + d];
    float4 yv = *(const float4*)&Y[(size_t)row * D + d];
    xv.x += yv.x; xv.y += yv.y; xv.z += yv.z; xv.w += yv.w;

    float s  = xv.x + xv.y + xv.z + xv.w;
    float sq = xv.x * xv.x + xv.y * xv.y + xv.z * xv.z + xv.w * xv.w;
#pragma unroll
    for (int off = 16; off; off >>= 1) {
        s  += __shfl_xor_sync(0xffffffffu, s,  off);
        sq += __shfl_xor_sync(0xffffffffu, sq, off);
    }
    if (lane == 0) { reds[wid] = s; redq[wid] = sq; }
    __syncthreads();
    s  = reds[0] + reds[1] + reds[2] + reds[3];
    sq = redq[0] + redq[1] + redq[2] + redq[3];

    float mu  = s * (1.0f / D);
    float var = sq * (1.0f / D) - mu * mu;
    float rstd = rsqrtf(var + EPS);

    float4 gv = *(const float4*)&g[d];
    float4 bv = *(const float4*)&beta[d];
    float4 o;
    o.x = (xv.x - mu) * rstd * gv.x + bv.x;
    o.y = (xv.y - mu) * rstd * gv.y + bv.y;
    o.z = (xv.z - mu) * rstd * gv.z + bv.z;
    o.w = (xv.w - mu) * rstd * gv.w + bv.w;
    *(float4*)&out[(size_t)row * D + d] = o;
}

// ---------------------------------------------------------------------------
// Launch
// ---------------------------------------------------------------------------
extern "C" void kernel_launch(void* const* d_in, const int* in_sizes, int n_in,
                              void* d_out, int out_size) {
    const int*   x     = (const int*)  d_in[0];
    const float* tab   = (const float*)d_in[1];
    const float* rowe  = (const float*)d_in[2];
    const float* cole  = (const float*)d_in[3];
    const float* Wq    = (const float*)d_in[4];
    const float* bq    = (const float*)d_in[5];
    const float* Wk    = (const float*)d_in[6];
    const float* bk    = (const float*)d_in[7];
    const float* Wv    = (const float*)d_in[8];
    const float* bv    = (const float*)d_in[9];
    const float* Wo    = (const float*)d_in[10];
    const float* bo    = (const float*)d_in[11];
    const float* ln1g  = (const float*)d_in[12];
    const float* ln1b  = (const float*)d_in[13];
    const float* W1    = (const float*)d_in[14];
    const float* b1    = (const float*)d_in[15];
    const float* W2    = (const float*)d_in[16];
    const float* b2    = (const float*)d_in[17];
    const float* ln2g  = (const float*)d_in[18];
    const float* ln2b  = (const float*)d_in[19];
    const float* Wh    = (const float*)d_in[20];
    const float* bh    = (const float*)d_in[21];
    float* out = (float*)d_out;

    float *h0, *q, *k, *v, *att, *o, *h1, *mid, *f, *h2;
    cudaGetSymbolAddress((void**)&h0,  g_h0);
    cudaGetSymbolAddress((void**)&q,   g_q);
    cudaGetSymbolAddress((void**)&k,   g_k);
    cudaGetSymbolAddress((void**)&v,   g_v);
    cudaGetSymbolAddress((void**)&att, g_att);
    cudaGetSymbolAddress((void**)&o,   g_o);
    cudaGetSymbolAddress((void**)&h1,  g_h1);
    cudaGetSymbolAddress((void**)&mid, g_mid);
    cudaGetSymbolAddress((void**)&f,   g_f);
    cudaGetSymbolAddress((void**)&h2,  g_h2);

    // 1. embedding + pos
    embed_kernel<<<NTOK, 128>>>(x, tab, rowe, cole, h0);

    // 2. Q,K,V projections
    gemm_bias<<<dim3(D / 128, NTOK / 128), 256>>>(h0, Wq, bq, q, NTOK, D, D, 0);
    gemm_bias<<<dim3(D / 128, NTOK / 128), 256>>>(h0, Wk, bk, k, NTOK, D, D, 0);
    gemm_bias<<<dim3(D / 128, NTOK / 128), 256>>>(h0, Wv, bv, v, NTOK, D, D, 0);

    // 3. fused local-causal attention
    attn_kernel<<<NTOK, 128>>>(q, k, v, att);

    // 4. output projection
    gemm_bias<<<dim3(D / 128, NTOK / 128), 256>>>(att, Wo, bo, o, NTOK, D, D, 0);

    // 5. residual + LN1
    add_ln_kernel<<<NTOK, 128>>>(h0, o, ln1g, ln1b, h1);

    // 6. FFN
    gemm_bias<<<dim3(DFF / 128, NTOK / 128), 256>>>(h1, W1, b1, mid, NTOK, DFF, D, 1);
    gemm_bias<<<dim3(D / 128, NTOK / 128), 256>>>(mid, W2, b2, f, NTOK, D, DFF, 0);

    // 7. residual + LN2
    add_ln_kernel<<<NTOK, 128>>>(h1, f, ln2g, ln2b, h2);

    // 8. vocab head -> d_out
    gemm_bias<<<dim3(VOCAB / 128, NTOK / 128), 256>>>(h2, Wh, bh, out, NTOK, VOCAB, D, 0);
}

// round 2
// speedup vs baseline: 1.0006x; 1.0006x over previous
#include <cuda_runtime.h>
#include <cuda_bf16.h>
#include <math.h>

// ---------------------------------------------------------------------------
// Problem constants
// ---------------------------------------------------------------------------
#define B 8
#define SEQ 1024
#define NROW 32
#define NCOL 32
#define WIN 9
#define D 512
#define DFF 1024
#define VOCAB 16384
#define NTOK (B * SEQ)   // 8192
#define EPS 1e-5f

// ---------------------------------------------------------------------------
// Scratch buffers (device globals: no allocation allowed)
// ---------------------------------------------------------------------------
__device__ float g_h0 [NTOK * D];    // embed + pos
__device__ float g_q  [NTOK * D];
__device__ float g_k  [NTOK * D];
__device__ float g_v  [NTOK * D];
__device__ float g_att[NTOK * D];    // attention output (pre O-proj)
__device__ float g_o  [NTOK * D];    // O-proj output
__device__ float g_h1 [NTOK * D];    // after LN1
__device__ float g_mid[NTOK * DFF];  // FFN hidden
__device__ float g_f  [NTOK * D];    // FFN output
__device__ float g_h2 [NTOK * D];    // after LN2

// ---------------------------------------------------------------------------
// Kernel 1: embedding gather + 2D positional encoding
// h0[b,s,:] = embed_tab[x[b,s],:] + [row_embed[s/32,:], col_embed[s%32,:]]
// one block (128 thr) per token row; float4 vectorized
// ---------------------------------------------------------------------------
__global__ void embed_kernel(const int* __restrict__ x,
                             const float* __restrict__ tab,
                             const float* __restrict__ rowe,
                             const float* __restrict__ cole,
                             float* __restrict__ h) {
    int qi = blockIdx.x;             // 0..8191
    int s  = qi & (SEQ - 1);
    int r  = s >> 5, c = s & 31;
    int tok = x[qi];
    int d = threadIdx.x * 4;

    float4 e = *(const float4*)&tab[(size_t)tok * D + d];
    float4 p;
    if (d < D / 2) p = *(const float4*)&rowe[r * (D / 2) + d];
    else           p = *(const float4*)&cole[c * (D / 2) + (d - D / 2)];
    e.x += p.x; e.y += p.y; e.z += p.z; e.w += p.w;
    *(float4*)&h[(size_t)qi * D + d] = e;
}

// ---------------------------------------------------------------------------
// Kernel 2: generic fp32 GEMM + bias (+ optional ReLU)
//   C[M,N] = A[M,K] @ B[K,N] + bias[N]
// 128x128 tile, BK=8, 256 threads, 8x8 per thread.
// All M,N multiples of 128; K multiple of 8 (holds for every call here).
// ---------------------------------------------------------------------------
__global__ void gemm_bias(const float* __restrict__ A,
                          const float* __restrict__ Bm,
                          const float* __restrict__ bias,
                          float* __restrict__ C,
                          int M, int N, int K, int relu) {
    __shared__ float As[8][128];
    __shared__ float Bs[8][128];

    int tid = threadIdx.x;
    int bm = blockIdx.y * 128;
    int bn = blockIdx.x * 128;

    int arow = tid >> 1;             // 0..127
    int acol = (tid & 1) * 4;        // 0 or 4
    int brow = tid >> 5;             // 0..7
    int bcol = (tid & 31) * 4;       // 0..124

    int ty = tid >> 4;               // 0..15
    int tx = tid & 15;               // 0..15

    float acc[8][8];
#pragma unroll
    for (int i = 0; i < 8; i++)
#pragma unroll
        for (int j = 0; j < 8; j++) acc[i][j] = 0.0f;

    for (int k0 = 0; k0 < K; k0 += 8) {
        float4 av = *(const float4*)&A[(size_t)(bm + arow) * K + k0 + acol];
        As[acol + 0][arow] = av.x;
        As[acol + 1][arow] = av.y;
        As[acol + 2][arow] = av.z;
        As[acol + 3][arow] = av.w;
        float4 bv = *(const float4*)&Bm[(size_t)(k0 + brow) * N + bn + bcol];
        *(float4*)&Bs[brow][bcol] = bv;
        __syncthreads();

#pragma unroll
        for (int kk = 0; kk < 8; kk++) {
            float a[8], bb[8];
#pragma unroll
            for (int i = 0; i < 8; i++) a[i] = As[kk][ty * 8 + i];
#pragma unroll
            for (int j = 0; j < 8; j++) bb[j] = Bs[kk][tx * 8 + j];
#pragma unroll
            for (int i = 0; i < 8; i++)
#pragma unroll
                for (int j = 0; j < 8; j++) acc[i][j] = fmaf(a[i], bb[j], acc[i][j]);
        }
        __syncthreads();
    }

#pragma unroll
    for (int i = 0; i < 8; i++) {
        int row = bm + ty * 8 + i;
#pragma unroll
        for (int j = 0; j < 8; j += 4) {
            int col = bn + tx * 8 + j;
            float4 o;
            o.x = acc[i][j + 0] + bias[col + 0];
            o.y = acc[i][j + 1] + bias[col + 1];
            o.z = acc[i][j + 2] + bias[col + 2];
            o.w = acc[i][j + 3] + bias[col + 3];
            if (relu) {
                o.x = fmaxf(o.x, 0.0f); o.y = fmaxf(o.y, 0.0f);
                o.z = fmaxf(o.z, 0.0f); o.w = fmaxf(o.w, 0.0f);
            }
            *(float4*)&C[(size_t)row * N + col] = o;
        }
    }
}

// ---------------------------------------------------------------------------
// Kernel 3: fused local-causal attention.
// One block (128 thr) per query token. Allowed keys: rows r-9..r, cols c-9..c+9,
// row r truncated at col c (causal). <= 181 keys.
// ---------------------------------------------------------------------------
__global__ void attn_kernel(const float* __restrict__ Q,
                            const float* __restrict__ K,
                            const float* __restrict__ V,
                            float* __restrict__ O) {
    int qi = blockIdx.x;
    int b = qi >> 10, s = qi & (SEQ - 1);
    int r = s >> 5, c = s & 31;
    int r0 = (r - WIN < 0) ? 0 : r - WIN;
    int c0 = (c - WIN < 0) ? 0 : c - WIN;
    int c1 = (c + WIN > 31) ? 31 : c + WIN;
    int wcols = c1 - c0 + 1;
    int nfull = r - r0;
    int nk = nfull * wcols + (c - c0 + 1);

    __shared__ float qv[D];
    __shared__ float sc[256];
    __shared__ int   kid[256];
    __shared__ float red[4];

    int tid = threadIdx.x;
    int lane = tid & 31, wid = tid >> 5;

    // load q row
    *(float4*)&qv[tid * 4] = *(const float4*)&Q[(size_t)qi * D + tid * 4];
    __syncthreads();

    const float scale = 0.044194173824159216f;  // 1/sqrt(512)
    const float* kbase = K + (size_t)b * SEQ * D;

    // scores: warp w handles keys w, w+4, ...
    for (int j = wid; j < nk; j += 4) {
        int row, col;
        if (j < nfull * wcols) { row = r0 + j / wcols; col = c0 + j % wcols; }
        else                   { row = r;             col = c0 + (j - nfull * wcols); }
        int kk = row * 32 + col;
        const float* krow = kbase + (size_t)kk * D;
        float sum = 0.0f;
#pragma unroll
        for (int t = 0; t < D / 32; t++)
            sum = fmaf(qv[lane + 32 * t], krow[lane + 32 * t], sum);
#pragma unroll
        for (int off = 16; off; off >>= 1)
            sum += __shfl_xor_sync(0xffffffffu, sum, off);
        if (lane == 0) { sc[j] = sum * scale; kid[j] = kk; }
    }
    __syncthreads();

    // block max
    float m = -1e30f;
    for (int j = tid; j < nk; j += 128) m = fmaxf(m, sc[j]);
#pragma unroll
    for (int off = 16; off; off >>= 1)
        m = fmaxf(m, __shfl_xor_sync(0xffffffffu, m, off));
    if (lane == 0) red[wid] = m;
    __syncthreads();
    m = fmaxf(fmaxf(red[0], red[1]), fmaxf(red[2], red[3]));

    // exp + sum
    float ssum = 0.0f;
    for (int j = tid; j < nk; j += 128) {
        float e = __expf(sc[j] - m);
        sc[j] = e;
        ssum += e;
    }
    __syncthreads();   // covers red reuse + sc writes
#pragma unroll
    for (int off = 16; off; off >>= 1)
        ssum += __shfl_xor_sync(0xffffffffu, ssum, off);
    if (lane == 0) red[wid] = ssum;
    __syncthreads();
    float inv = 1.0f / (red[0] + red[1] + red[2] + red[3]);

    // weighted sum of V rows: thread t owns dims [4t, 4t+4)
    const float* vbase = V + (size_t)b * SEQ * D;
    int d = tid * 4;
    float4 acc = make_float4(0.f, 0.f, 0.f, 0.f);
    for (int j = 0; j < nk; j++) {
        float w = sc[j] * inv;
        float4 v = *(const float4*)&vbase[(size_t)kid[j] * D + d];
        acc.x = fmaf(w, v.x, acc.x);
        acc.y = fmaf(w, v.y, acc.y);
        acc.z = fmaf(w, v.z, acc.z);
        acc.w = fmaf(w, v.w, acc.w);
    }
    *(float4*)&O[(size_t)qi * D + d] = acc;
}

// ---------------------------------------------------------------------------
// Kernel 4: out = LayerNorm(X + Y) * g + b   (row-wise over D=512)
// One block (128 thr) per row.
// ---------------------------------------------------------------------------
__global__ void add_ln_kernel(const float* __restrict__ X,
                              const float* __restrict__ Y,
                              const float* __restrict__ g,
                              const float* __restrict__ beta,
                              float* __restrict__ out) {
    int row = blockIdx.x;
    int tid = threadIdx.x;
    int lane = tid & 31, wid = tid >> 5;
    __shared__ float reds[4], redq[4];

    int d = tid * 4;
    float4 xv = *(const float4*)&X[(size_t)row * D + d];
    float4 yv = *(const float4*)&Y[(size_t)row * D + d];
    xv.x += yv.x; xv.y += yv.y; xv.z += yv.z; xv.w += yv.w;

    float s  = xv.x + xv.y + xv.z + xv.w;
    float sq = xv.x * xv.x + xv.y * xv.y + xv.z * xv.z + xv.w * xv.w;
#pragma unroll
    for (int off = 16; off; off >>= 1) {
        s  += __shfl_xor_sync(0xffffffffu, s,  off);
        sq += __shfl_xor_sync(0xffffffffu, sq, off);
    }
    if (lane == 0) { reds[wid] = s; redq[wid] = sq; }
    __syncthreads();
    s  = reds[0] + reds[1] + reds[2] + reds[3];
    sq = redq[0] + redq[1] + redq[2] + redq[3];

    float mu  = s * (1.0f / D);
    float var = sq * (1.0f / D) - mu * mu;
    float rstd = rsqrtf(var + EPS);

    float4 gv = *(const float4*)&g[d];
    float4 bv = *(const float4*)&beta[d];
    float4 o;
    o.x = (xv.x - mu) * rstd * gv.x + bv.x;
    o.y = (xv.y - mu) * rstd * gv.y + bv.y;
    o.z = (xv.z - mu) * rstd * gv.z + bv.z;
    o.w = (xv.w - mu) * rstd * gv.w + bv.w;
    *(float4*)&out[(size_t)row * D + d] = o;
}

// ---------------------------------------------------------------------------
// Launch
// ---------------------------------------------------------------------------
extern "C" void kernel_launch(void* const* d_in, const int* in_sizes, int n_in,
                              void* d_out, int out_size) {
    const int*   x     = (const int*)  d_in[0];
    const float* tab   = (const float*)d_in[1];
    const float* rowe  = (const float*)d_in[2];
    const float* cole  = (const float*)d_in[3];
    const float* Wq    = (const float*)d_in[4];
    const float* bq    = (const float*)d_in[5];
    const float* Wk    = (const float*)d_in[6];
    const float* bk    = (const float*)d_in[7];
    const float* Wv    = (const float*)d_in[8];
    const float* bv    = (const float*)d_in[9];
    const float* Wo    = (const float*)d_in[10];
    const float* bo    = (const float*)d_in[11];
    const float* ln1g  = (const float*)d_in[12];
    const float* ln1b  = (const float*)d_in[13];
    const float* W1    = (const float*)d_in[14];
    const float* b1    = (const float*)d_in[15];
    const float* W2    = (const float*)d_in[16];
    const float* b2    = (const float*)d_in[17];
    const float* ln2g  = (const float*)d_in[18];
    const float* ln2b  = (const float*)d_in[19];
    const float* Wh    = (const float*)d_in[20];
    const float* bh    = (const float*)d_in[21];
    float* out = (float*)d_out;

    float *h0, *q, *k, *v, *att, *o, *h1, *mid, *f, *h2;
    cudaGetSymbolAddress((void**)&h0,  g_h0);
    cudaGetSymbolAddress((void**)&q,   g_q);
    cudaGetSymbolAddress((void**)&k,   g_k);
    cudaGetSymbolAddress((void**)&v,   g_v);
    cudaGetSymbolAddress((void**)&att, g_att);
    cudaGetSymbolAddress((void**)&o,   g_o);
    cudaGetSymbolAddress((void**)&h1,  g_h1);
    cudaGetSymbolAddress((void**)&mid, g_mid);
    cudaGetSymbolAddress((void**)&f,   g_f);
    cudaGetSymbolAddress((void**)&h2,  g_h2);

    // 1. embedding + pos
    embed_kernel<<<NTOK, 128>>>(x, tab, rowe, cole, h0);

    // 2. Q,K,V projections
    gemm_bias<<<dim3(D / 128, NTOK / 128), 256>>>(h0, Wq, bq, q, NTOK, D, D, 0);
    gemm_bias<<<dim3(D / 128, NTOK / 128), 256>>>(h0, Wk, bk, k, NTOK, D, D, 0);
    gemm_bias<<<dim3(D / 128, NTOK / 128), 256>>>(h0, Wv, bv, v, NTOK, D, D, 0);

    // 3. fused local-causal attention
    attn_kernel<<<NTOK, 128>>>(q, k, v, att);

    // 4. output projection
    gemm_bias<<<dim3(D / 128, NTOK / 128), 256>>>(att, Wo, bo, o, NTOK, D, D, 0);

    // 5. residual + LN1
    add_ln_kernel<<<NTOK, 128>>>(h0, o, ln1g, ln1b, h1);

    // 6. FFN
    gemm_bias<<<dim3(DFF / 128, NTOK / 128), 256>>>(h1, W1, b1, mid, NTOK, DFF, D, 1);
    gemm_bias<<<dim3(D / 128, NTOK / 128), 256>>>(mid, W2, b2, f, NTOK, D, DFF, 0);

    // 7. residual + LN2
    add_ln_kernel<<<NTOK, 128>>>(h1, f, ln2g, ln2b, h2);

    // 8. vocab head -> d_out
    gemm_bias<<<dim3(VOCAB / 128, NTOK / 128), 256>>>(h2, Wh, bh, out, NTOK, VOCAB, D, 0);
}